// round 17
// baseline (speedup 1.0000x reference)
#include <cuda_runtime.h>
#include <cuda_bf16.h>
#include <cstdint>

#define N_NODES 32
#define M_EDGES 256
#define H1 128
#define H2 256
#define H3 128
#define NPAIR 1024
#define EPSF 1e-9f
#define GRID_MLP 152
#define NTHREADS 512
#define FULL_ROUNDS 13          // 152*13 = 1976 full tiles
#define NHALF 144               // remaining 72 tiles -> 144 half-tiles (64 rows)

typedef uint32_t u32;

// ---------------- scratch (no allocations allowed) ----------------
__device__ float g_aT[N_NODES * H1];             // s-major: [s][k]
__device__ float g_bT[N_NODES * H1];             // t-major: [t][k]
__device__ float g_cT[H1 * M_EDGES];             // k-major: [k][e]
__device__ float g_preds4[4][NPAIR * M_EDGES];   // per-warp-column partial preds
__device__ float g_delta[NPAIR * N_NODES];
__device__ int   g_ctr;                          // last-block-done counter
// 8 cyclic pre-swizzled weight pieces, 32KB each: [hi 16KB | lo 16KB]
__device__ __align__(16) unsigned char g_Bseq[8][32768];

// ---------------- smem layout (bytes) ----------------
// A1 ping-pong: 2 x (hi 32K + lo 32K) = 128K; A2 32K; B ring 64K  => 224K
#define SM_A1(b) ((u32)(b) * 65536u)   // hi at +0, lo at +32768
#define SM_A2H 131072
#define SM_A2L 147456
#define SM_B0  163840
#define SM_B1  196608
#define SM_TOTAL 229376

// ---------------- PTX helpers ----------------
__device__ __forceinline__ u32 smem_u32(const void* p) {
    u32 a; asm("{ .reg .u64 t; cvta.to.shared.u64 t, %1; cvt.u32.u64 %0, t; }" : "=r"(a) : "l"(p));
    return a;
}
__device__ __forceinline__ void ldm_x4(u32 r[4], u32 addr) {
    asm volatile("ldmatrix.sync.aligned.m8n8.x4.shared.b16 {%0,%1,%2,%3}, [%4];"
                 : "=r"(r[0]), "=r"(r[1]), "=r"(r[2]), "=r"(r[3]) : "r"(addr));
}
__device__ __forceinline__ void ldm_x4_t(u32 r[4], u32 addr) {
    asm volatile("ldmatrix.sync.aligned.m8n8.x4.trans.shared.b16 {%0,%1,%2,%3}, [%4];"
                 : "=r"(r[0]), "=r"(r[1]), "=r"(r[2]), "=r"(r[3]) : "r"(addr));
}
__device__ __forceinline__ void mma16816(float c[4], const u32 a[4], const u32 b[2]) {
    asm volatile("mma.sync.aligned.m16n8k16.row.col.f32.bf16.bf16.f32 "
                 "{%0,%1,%2,%3}, {%4,%5,%6,%7}, {%8,%9}, {%0,%1,%2,%3};"
                 : "+f"(c[0]), "+f"(c[1]), "+f"(c[2]), "+f"(c[3])
                 : "r"(a[0]), "r"(a[1]), "r"(a[2]), "r"(a[3]), "r"(b[0]), "r"(b[1]));
}
__device__ __forceinline__ void cp16(u32 dst, const void* src) {
    asm volatile("cp.async.cg.shared.global [%0], [%1], 16;" :: "r"(dst), "l"(src) : "memory");
}
__device__ __forceinline__ void cp_commit() {
    asm volatile("cp.async.commit_group;" ::: "memory");
}
__device__ __forceinline__ void cp_wait0() {
    asm volatile("cp.async.wait_group 0;" ::: "memory");
}
__device__ __forceinline__ __nv_bfloat162 split_hi(float v0, float v1, __nv_bfloat162& lo) {
    __nv_bfloat162 hi;
    hi.x = __float2bfloat16(v0); hi.y = __float2bfloat16(v1);
    lo.x = __float2bfloat16(v0 - __bfloat162float(hi.x));
    lo.y = __float2bfloat16(v1 - __bfloat162float(hi.y));
    return hi;
}

// ---------------- kernel 1: factored layer-1 partials + weight split/swizzle ----------------
__global__ void prep_all_kernel(const float* __restrict__ emb,
                                const int*   __restrict__ edges,
                                const float* __restrict__ W1,
                                const float* __restrict__ b1,
                                const float* __restrict__ W2,
                                const float* __restrict__ W3)
{
    int idx = blockIdx.x * blockDim.x + threadIdx.x;
    if (idx == 0) g_ctr = 0;                     // reset last-block counter (deterministic per replay)
    if (idx < 2 * H1 * N_NODES) {
        int sec = idx >> 12;
        int r = idx & 4095;
        int s = r >> 7, k = r & 127;
        const float* w = W1 + (sec ? (32 * H1) : 0) + k;
        float acc0 = 0.f, acc1 = 0.f;
        #pragma unroll
        for (int j = 0; j < 32; j += 2) {
            acc0 = fmaf(emb[s * 32 + j],     w[j * H1],       acc0);
            acc1 = fmaf(emb[s * 32 + j + 1], w[(j + 1) * H1], acc1);
        }
        (sec ? g_bT : g_aT)[s * H1 + k] = acc0 + acc1;
    } else if (idx < 40960) {
        int r = idx - 2 * H1 * N_NODES;          // [0, 32768)
        int e = r >> 7, k = r & 127;
        int u = edges[2 * e], v = edges[2 * e + 1];
        const float* wu = W1 + 64 * H1 + k;
        const float* wv = W1 + 96 * H1 + k;
        float acc0 = b1[k], acc1 = 0.f;
        #pragma unroll
        for (int j = 0; j < 32; j++) {
            acc0 = fmaf(emb[u * 32 + j], wu[j * H1], acc0);
            acc1 = fmaf(emb[v * 32 + j], wv[j * H1], acc1);
        }
        g_cT[k * M_EDGES + e] = acc0 + acc1;
    } else {
        int widx = idx - 40960;                  // [0, 65536)
        int p = widx >> 13;                      // piece 0..7
        int r = widx & 8191;
        float w; u32 off;
        if ((p & 1) == 0) {
            int c = p >> 1;
            int nn = r & 63, k = r >> 6;
            w = W2[k * H2 + c * 64 + nn];
            off = (u32)(nn * 256 + k * 2) ^ (u32)((nn & 7) << 4);
        } else {
            int c = p >> 1;
            int n = r & 127, kl = r >> 7;
            w = W3[(c * 64 + kl) * H3 + n];
            off = (u32)(n * 128 + kl * 2) ^ (u32)((n & 7) << 4);
        }
        __nv_bfloat16 hi = __float2bfloat16(w);
        __nv_bfloat16 lo = __float2bfloat16(w - __bfloat162float(hi));
        *(__nv_bfloat16*)&g_Bseq[p][off] = hi;
        *(__nv_bfloat16*)&g_Bseq[p][off + 16384] = lo;
    }
}

// ================= fused MLP: persistent, 512 threads, cp.async B ring + A1 ping-pong =================
__device__ __forceinline__ void issue_piece(u32 dstb, int p, int tid)
{
    const char* src = (const char*)g_Bseq[p];
    #pragma unroll
    for (int i = 0; i < 4; i++) {
        int f = (tid + i * NTHREADS) * 16;
        cp16(dstb + f, src + f);
    }
    cp_commit();
}

__global__ void __launch_bounds__(NTHREADS, 1)
mlp_fused_kernel(const float* __restrict__ b2, const float* __restrict__ b3,
                 const float* __restrict__ W4)
{
    extern __shared__ unsigned char smp[];
    const u32 sb = smem_u32(smp);
    const int tid  = threadIdx.x;
    const int wid  = tid >> 5;            // 0..15
    const int lane = tid & 31;
    const int bid  = blockIdx.x;

    // l2 warp layout: 4m x 4n -> warp tile 32m x 16n (N local 64)
    const int m0_2 = (wid >> 2) * 32;
    const int n0_2 = (wid & 3) * 16;
    // l3 warp layout: 4m x 4n -> warp tile 32m x 32n (N 128)
    const int m0_3 = (wid >> 2) * 32;
    const int wn3  = wid & 3;
    const int n0_3 = wn3 * 32;
    const int mgrp = wid >> 2;

    // fragment lane constants
    const int a_krow = (lane & 7) + ((lane >> 4) << 3);     // trans-A (l2)
    const int a_cb   = ((lane >> 3) & 1) << 4;
    const int a_row  = (lane & 7) + ((lane >> 3) & 1) * 8;  // non-trans A (l3)
    const int a_kb3  = (lane >> 4) << 4;
    const int b_nrow = ((lane >> 4) << 3) + (lane & 7);     // B rows
    const int b_kb   = ((lane >> 3) & 1) << 4;
    const u32 xl     = (u32)((lane & 7) << 4);
    const u32 xk     = (u32)((a_krow & 7) << 4);

    const u32 bufs[2] = {sb + SM_B0, sb + SM_B1};

    // full-tile h1 build into A1[bufB] (all 16 warps)
    auto build_full = [&](int pair, int eb, int bufB) {
        const int s = pair >> 5, t = pair & 31;
        const u32 aH = SM_A1(bufB), aL = aH + 32768;
        #pragma unroll
        for (int j = 0; j < 8; j++) {
            int k = wid + j * 16;
            float base = g_aT[s * H1 + k] + g_bT[t * H1 + k];
            u32 swz = (u32)((k & 7) << 4);
            int m = lane * 4;
            float4 c4 = *(const float4*)&g_cT[k * M_EDGES + eb + m];
            float v0 = fmaxf(base + c4.x, 0.f);
            float v1 = fmaxf(base + c4.y, 0.f);
            float v2 = fmaxf(base + c4.z, 0.f);
            float v3 = fmaxf(base + c4.w, 0.f);
            __nv_bfloat162 lp0, hp0 = split_hi(v0, v1, lp0);
            __nv_bfloat162 lp1, hp1 = split_hi(v2, v3, lp1);
            u32 off = ((u32)(k * 256 + m * 2)) ^ swz;
            *(__nv_bfloat162*)(smp + aH + off)     = hp0;
            *(__nv_bfloat162*)(smp + aH + off + 4) = hp1;
            *(__nv_bfloat162*)(smp + aL + off)     = lp0;
            *(__nv_bfloat162*)(smp + aL + off + 4) = lp1;
        }
    };
    // half-tile (64 row) h1 build
    auto build_half = [&](int pair, int eb, int bufB) {
        const int s = pair >> 5, t = pair & 31;
        const u32 aH = SM_A1(bufB), aL = aH + 32768;
        #pragma unroll
        for (int j = 0; j < 4; j++) {
            int k = wid + ((lane >> 4) << 4) + j * 32;
            float base = g_aT[s * H1 + k] + g_bT[t * H1 + k];
            u32 swz = (u32)((k & 7) << 4);
            int m = (lane & 15) * 4;
            float4 c4 = *(const float4*)&g_cT[k * M_EDGES + eb + m];
            float v0 = fmaxf(base + c4.x, 0.f);
            float v1 = fmaxf(base + c4.y, 0.f);
            float v2 = fmaxf(base + c4.z, 0.f);
            float v3 = fmaxf(base + c4.w, 0.f);
            __nv_bfloat162 lp0, hp0 = split_hi(v0, v1, lp0);
            __nv_bfloat162 lp1, hp1 = split_hi(v2, v3, lp1);
            u32 off = ((u32)(k * 256 + m * 2)) ^ swz;
            *(__nv_bfloat162*)(smp + aH + off)     = hp0;
            *(__nv_bfloat162*)(smp + aH + off + 4) = hp1;
            *(__nv_bfloat162*)(smp + aL + off)     = lp0;
            *(__nv_bfloat162*)(smp + aL + off + 4) = lp1;
        }
    };

    // One tile. h1 must already be in A1[bufB]. If hasNext, builds next tile's h1
    // into A1[bufB^1] during chunk 2's L3 MMA shadow.
    auto do_tile = [&](int pair, int eb, int mgroups, int bufB,
                       int nextPair, int nextEb, bool hasNext) {
        const bool act = (mgrp < mgroups);
        const u32 a1H = SM_A1(bufB), a1L = a1H + 32768;

        cp_wait0();
        __syncthreads();            // A1[bufB] visible + B2 piece 0 ready
                                    // (also guards A2 reuse vs prev tile's last L3)

        float acc3[2][4][4];
        #pragma unroll
        for (int mt = 0; mt < 2; mt++)
            #pragma unroll
            for (int nt = 0; nt < 4; nt++)
                #pragma unroll
                for (int i = 0; i < 4; i++) acc3[mt][nt][i] = 0.f;

        #pragma unroll 1
        for (int c = 0; c < 4; c++) {
            const u32 bb2 = bufs[0];       // even pieces -> buf0
            const u32 bb3 = bufs[1];       // odd pieces -> buf1

            // prefetch B3 sub c
            issue_piece(bb3, 2 * c + 1, tid);

            if (act) {
                // ---- L2 sub-MMA: acc2 = h1 x B2[:, c*64 .. c*64+64) ----
                float acc2[2][2][4];
                #pragma unroll
                for (int mt = 0; mt < 2; mt++)
                    #pragma unroll
                    for (int nt = 0; nt < 2; nt++)
                        #pragma unroll
                        for (int i = 0; i < 4; i++) acc2[mt][nt][i] = 0.f;

                #pragma unroll
                for (int ks = 0; ks < 8; ks++) {
                    u32 ah[2][4], al[2][4];
                    #pragma unroll
                    for (int mt = 0; mt < 2; mt++) {
                        u32 off = ((u32)((ks * 16 + a_krow) * 256 + (m0_2 + mt * 16) * 2 + a_cb)) ^ xk;
                        ldm_x4_t(ah[mt], sb + a1H + off);
                        ldm_x4_t(al[mt], sb + a1L + off);
                    }
                    u32 bh[4], bl[4];
                    {
                        u32 off = ((u32)((n0_2 + b_nrow) * 256 + ks * 32 + b_kb)) ^ xl;
                        ldm_x4(bh, bb2 + off);
                        ldm_x4(bl, bb2 + 16384 + off);
                    }
                    #pragma unroll
                    for (int mt = 0; mt < 2; mt++)
                        #pragma unroll
                        for (int nt = 0; nt < 2; nt++) {
                            const u32* Bh = &bh[nt * 2];
                            const u32* Bl = &bl[nt * 2];
                            mma16816(acc2[mt][nt], ah[mt], Bh);
                            mma16816(acc2[mt][nt], ah[mt], Bl);
                            mma16816(acc2[mt][nt], al[mt], Bh);
                        }
                }

                // ---- h2 epilogue -> A2 [rows m][64k] ----
                #pragma unroll
                for (int nt = 0; nt < 2; nt++) {
                    int nl = n0_2 + nt * 8 + (lane & 3) * 2;
                    int gc = c * 64 + nl;
                    float bx = __ldg(&b2[gc]), by = __ldg(&b2[gc + 1]);
                    #pragma unroll
                    for (int mt = 0; mt < 2; mt++) {
                        #pragma unroll
                        for (int h = 0; h < 2; h++) {
                            int row = m0_2 + mt * 16 + (lane >> 2) + h * 8;
                            float v0 = fmaxf(acc2[mt][nt][h * 2 + 0] + bx, 0.f);
                            float v1 = fmaxf(acc2[mt][nt][h * 2 + 1] + by, 0.f);
                            __nv_bfloat162 lp, hp = split_hi(v0, v1, lp);
                            u32 off = ((u32)(row * 128 + nl * 2)) ^ (u32)((row & 7) << 4);
                            *(__nv_bfloat162*)(smp + SM_A2H + off) = hp;
                            *(__nv_bfloat162*)(smp + SM_A2L + off) = lp;
                        }
                    }
                }
            }
            cp_wait0();
            __syncthreads();        // A2 visible + B3 piece ready

            // prefetch next even piece (wraps to 0 for next tile)
            issue_piece(bb2, (2 * c + 2) & 7, tid);

            if (act) {
                // ---- L3 sub-MMA: acc3 += h2c x B3[c*64.., :] ----
                #pragma unroll
                for (int ks = 0; ks < 4; ks++) {
                    u32 ah[2][4], al[2][4];
                    #pragma unroll
                    for (int mt = 0; mt < 2; mt++) {
                        u32 off = ((u32)((m0_3 + mt * 16 + a_row) * 128 + ks * 32 + a_kb3)) ^ xl;
                        ldm_x4(ah[mt], sb + SM_A2H + off);
                        ldm_x4(al[mt], sb + SM_A2L + off);
                    }
                    u32 bh[2][4], bl[2][4];
                    #pragma unroll
                    for (int np = 0; np < 2; np++) {
                        u32 off = ((u32)((n0_3 + np * 16 + b_nrow) * 128 + ks * 32 + b_kb)) ^ xl;
                        ldm_x4(bh[np], bb3 + off);
                        ldm_x4(bl[np], bb3 + 16384 + off);
                    }
                    #pragma unroll
                    for (int mt = 0; mt < 2; mt++)
                        #pragma unroll
                        for (int nt = 0; nt < 4; nt++) {
                            const u32* Bh = &bh[nt >> 1][(nt & 1) * 2];
                            const u32* Bl = &bl[nt >> 1][(nt & 1) * 2];
                            mma16816(acc3[mt][nt], ah[mt], Bh);
                            mma16816(acc3[mt][nt], ah[mt], Bl);
                            mma16816(acc3[mt][nt], al[mt], Bh);
                        }
                }
            }

            // ---- hidden h1 prebuild for the NEXT tile (under chunk-2's L3 shadow) ----
            if (hasNext && c == 2)
                build_full(nextPair, nextEb, bufB ^ 1);

            if (c < 3) {            // last chunk: covered by next tile's start barrier
                cp_wait0();
                __syncthreads();    // A2 free for next epilogue + next B2 ready
            }
        }

        // ---- layer 4: partial pred per warp-column -> g_preds4 (no barriers) ----
        if (act) {
            #pragma unroll
            for (int mt = 0; mt < 2; mt++) {
                #pragma unroll
                for (int h = 0; h < 2; h++) {
                    float part = 0.f;
                    #pragma unroll
                    for (int nt = 0; nt < 4; nt++) {
                        int cc = n0_3 + nt * 8 + (lane & 3) * 2;
                        float h0 = fmaxf(acc3[mt][nt][h * 2 + 0] + __ldg(&b3[cc]), 0.f);
                        float h1 = fmaxf(acc3[mt][nt][h * 2 + 1] + __ldg(&b3[cc + 1]), 0.f);
                        part = fmaf(h0, __ldg(&W4[cc]), part);
                        part = fmaf(h1, __ldg(&W4[cc + 1]), part);
                    }
                    part += __shfl_xor_sync(0xffffffffu, part, 1);
                    part += __shfl_xor_sync(0xffffffffu, part, 2);
                    if ((lane & 3) == 0) {
                        int row = m0_3 + mt * 16 + (lane >> 2) + h * 8;
                        g_preds4[wn3][pair * M_EDGES + eb + row] = part;
                    }
                }
            }
        }
    };

    // prefetch piece 0 into buf 0; build tile 0's h1 into A1[0]
    issue_piece(bufs[0], 0, tid);
    build_full(bid >> 1, (bid & 1) * 128, 0);

    // ---- 13 uniform full tiles per CTA (h1 ping-pong prebuilt) ----
    int tile = bid;
    #pragma unroll 1
    for (int i = 0; i < FULL_ROUNDS; i++, tile += GRID_MLP) {
        int ntile = tile + GRID_MLP;
        do_tile(tile >> 1, (tile & 1) * 128, 4, i & 1,
                ntile >> 1, (ntile & 1) * 128, i < FULL_ROUNDS - 1);
    }

    // ---- remainder: 144 half-tiles (tiles 1976..2047 split in two) ----
    if (bid < NHALF) {
        int t2 = GRID_MLP * FULL_ROUNDS + (bid >> 1);
        int pair = t2 >> 1;
        int eb = (t2 & 1) * 128 + (bid & 1) * 64;
        build_half(pair, eb, 1);           // A1[1]: last read finished at tile-12 start barrier
        do_tile(pair, eb, 2, 1, 0, 0, false);
    }
    cp_wait0();
}

// ---------------- kernel 3: fused partial-sum + scatter + power iteration + final reduce ----------------
__global__ void power_kernel(const int* __restrict__ edges, const float* __restrict__ b4,
                             float* __restrict__ out)
{
    __shared__ float As[8][1024];
    __shared__ float red2[8][33];
    __shared__ int   isLast;
    const int wid  = threadIdx.x >> 5;
    const int lane = threadIdx.x & 31;
    const int p    = blockIdx.x * 8 + wid;
    float* A = As[wid];
    const float b4v = __ldg(&b4[0]);

    #pragma unroll
    for (int i = lane; i < 1024; i += 32) A[i] = 0.f;
    __syncwarp();

    #pragma unroll
    for (int j = 0; j < 8; j++) {
        int e = j * 32 + lane;
        int base = p * M_EDGES + e;
        float pred = ((g_preds4[0][base] + g_preds4[1][base])
                    + (g_preds4[2][base] + g_preds4[3][base])) + b4v;
        int u = edges[2 * e], v = edges[2 * e + 1];
        atomicAdd(&A[u * 32 + v], pred);
    }
    __syncwarp();

    const int s = p >> 5, t = p & 31;
    if (lane == 0) A[s * 32 + s] += 1.f;
    __syncwarp();

    float col[32];                       // A[:, lane]
    #pragma unroll
    for (int u = 0; u < 32; u++) col[u] = A[u * 32 + lane];

    // Power iteration with sparse normalization (direction-preserving scalar).
    float x = 1.0f / 32.0f;
    #pragma unroll 1
    for (int it = 0; it < 50; it++) {
        float a0 = 0.f, a1 = 0.f, a2 = 0.f, a3 = 0.f;
        #pragma unroll
        for (int u = 0; u < 32; u += 4) {
            a0 = fmaf(__shfl_sync(0xffffffffu, x, u),     col[u],     a0);
            a1 = fmaf(__shfl_sync(0xffffffffu, x, u + 1), col[u + 1], a1);
            a2 = fmaf(__shfl_sync(0xffffffffu, x, u + 2), col[u + 2], a2);
            a3 = fmaf(__shfl_sync(0xffffffffu, x, u + 3), col[u + 3], a3);
        }
        float acc = (a0 + a1) + (a2 + a3);
        if (((it & 3) == 3) || it == 49) {
            float ss = acc * acc;
            #pragma unroll
            for (int o = 16; o > 0; o >>= 1)
                ss += __shfl_xor_sync(0xffffffffu, ss, o);
            x = acc / (sqrtf(ss) + EPSF);
        } else {
            x = acc;
        }
    }
    float xs = __shfl_sync(0xffffffffu, x, s);
    float d = (s != t) ? x / (xs + EPSF) : 0.f;
    g_delta[p * 32 + lane] = d;

    // ---- last-block-done global reduction (deterministic order) ----
    __syncthreads();
    if (threadIdx.x == 0) {
        __threadfence();
        int done = atomicAdd(&g_ctr, 1);
        isLast = (done == gridDim.x - 1) ? 1 : 0;
    }
    __syncthreads();
    if (isLast) {
        __threadfence();
        int v = threadIdx.x & 31, g = threadIdx.x >> 5;   // 8 groups x 32
        float acc = 0.f;
        #pragma unroll 8
        for (int pp = g; pp < NPAIR; pp += 8)
            acc += g_delta[pp * 32 + v];
        red2[g][v] = acc;
        __syncthreads();
        if (g == 0) {
            float r = ((red2[0][v] + red2[1][v]) + (red2[2][v] + red2[3][v]))
                    + ((red2[4][v] + red2[5][v]) + (red2[6][v] + red2[7][v]));
            float tot = r;
            #pragma unroll
            for (int o = 16; o > 0; o >>= 1)
                tot += __shfl_xor_sync(0xffffffffu, tot, o);
            out[v] = r / tot;
        }
    }
}

// ---------------- launch ----------------
extern "C" void kernel_launch(void* const* d_in, const int* in_sizes, int n_in,
                              void* d_out, int out_size)
{
    (void)in_sizes; (void)n_in; (void)out_size;
    const float* emb   = (const float*)d_in[1];
    const int*   edges = (const int*)  d_in[2];
    const float* W1 = (const float*)d_in[3];
    const float* b1 = (const float*)d_in[4];
    const float* W2 = (const float*)d_in[5];
    const float* b2 = (const float*)d_in[6];
    const float* W3 = (const float*)d_in[7];
    const float* b3 = (const float*)d_in[8];
    const float* W4 = (const float*)d_in[9];
    const float* b4 = (const float*)d_in[10];
    float* out = (float*)d_out;

    static int attr_set = 0;
    if (!attr_set) {
        cudaFuncSetAttribute(mlp_fused_kernel, cudaFuncAttributeMaxDynamicSharedMemorySize, SM_TOTAL);
        attr_set = 1;
    }

    prep_all_kernel <<<416, 256>>>(emb, edges, W1, b1, W2, W3);
    mlp_fused_kernel<<<GRID_MLP, NTHREADS, SM_TOTAL>>>(b2, b3, W4);
    power_kernel    <<<128, 256>>>(edges, b4, out);
}